// round 3
// baseline (speedup 1.0000x reference)
#include <cuda_runtime.h>
#include <math.h>

#define NV 1024
#define NB 16
#define EGOS_PER_BLOCK 16
#define SLOTS 8
#define THREADS (EGOS_PER_BLOCK * SLOTS)   // 128

// Precomputed per-vehicle SoA: {x, y, cos(psi), sin(psi)} and v.
__device__ float4 g_cand[NB * NV];
__device__ float  g_cv[NB * NV];

__global__ void prep_kernel(const float* __restrict__ state)
{
    int idx = blockIdx.x * blockDim.x + threadIdx.x;   // idx = bat*NV + i
    if (idx >= NB * NV) return;
    const float* s = state + (size_t)idx * 5;
    float x = s[0], y = s[1], v = s[2], psi = s[3];
    float sp, cp;
    sincosf(psi, &sp, &cp);
    g_cand[idx] = make_float4(x, y, cp, sp);
    g_cv[idx] = v;
}

__global__ __launch_bounds__(THREADS)
void rulepolicy_kernel(const float* __restrict__ lengths,
                       const float* __restrict__ v0p,
                       const float* __restrict__ s0p,
                       const float* __restrict__ dthp,
                       const float* __restrict__ amaxp,
                       const float* __restrict__ bp,
                       float* __restrict__ out)
{
    __shared__ float4 cand[NV];
    __shared__ float  cv[NV];

    const int bat = blockIdx.y;
    const int t = threadIdx.x;
    const int base = bat * NV;

    for (int i = t; i < NV; i += THREADS) {
        cand[i] = g_cand[base + i];
        cv[i]   = g_cv[base + i];
    }
    __syncthreads();

    const int slot = t & (SLOTS - 1);
    const int jl   = blockIdx.x * EGOS_PER_BLOCK + (t >> 3);

    const float4 ego = cand[jl];
    const float  vj  = cv[jl];
    const float xj = ego.x, yj = ego.y, cj = ego.z, sj = ego.w;

    const float C20SQ = 0.8830222215594891f;   // cos^2(20deg)
    const float C45   = 0.7071067811865476f;   // cos(45deg)
    const float INF   = __int_as_float(0x7f800000);

    float best0 = INF, best1 = INF;
    int   idx0 = 0, idx1 = 0;
    int   stop0 = 0, stop1 = 0;

    // 128 pairs per thread; 2-wide ILP; unrolled so LDS uses immediate offsets.
    #pragma unroll 8
    for (int k = 0; k < NV / SLOTS; k += 2) {
        const int i0 = slot + k * SLOTS;
        const int i1 = i0 + SLOTS;
        float4 ca = cand[i0];
        float4 cb = cand[i1];
        float cva = cv[i0];
        float cvb = cv[i1];

        float dxa = ca.x - xj, dya = ca.y - yj;
        float dxb = cb.x - xj, dyb = cb.y - yj;
        float r2a = fmaf(dxa, dxa, dya * dya);
        float r2b = fmaf(dxb, dxb, dyb * dyb);
        float nda = fmaf(dxa, cj, dya * sj);           // dr * cos(delpsi)
        float ndb = fmaf(dxb, cj, dyb * sj);
        float n2a = nda * nda;
        float n2b = ndb * ndb;

        // Leader: nd>0 && nd^2 > r2*cos^2(20).  min(nd, n2 - r2*C20SQ) > 0
        float sa = fminf(nda, fmaf(-C20SQ, r2a, n2a));
        float sb = fminf(ndb, fmaf(-C20SQ, r2b, n2b));
        float ea = (sa > 0.0f) ? nda : INF;
        float eb = (sb > 0.0f) ? ndb : INF;
        if (ea < best0) { best0 = ea; idx0 = i0; }
        if (eb < best1) { best1 = eb; idx1 = i1; }

        // Stop: dr<20 & |delpsi|<60 (nd>0 & n2>r2/4) & |dpsi|>45 & v_i>v_j.
        float cpda = fmaf(ca.w, sj, ca.z * cj);        // cos(psi_i - psi_j)
        float cpdb = fmaf(cb.w, sj, cb.z * cj);
        stop0 |= (int)((r2a < 400.0f) & (nda > 0.0f) & (n2a > 0.25f * r2a)
                       & (cpda < C45) & (cva > vj));
        stop1 |= (int)((r2b < 400.0f) & (ndb > 0.0f) & (n2b > 0.25f * r2b)
                       & (cpdb < C45) & (cvb > vj));
    }

    // Merge dual accumulators (tie -> smaller index).
    float best = best0; int bidx = idx0;
    if (best1 < best || (best1 == best && idx1 < bidx)) { best = best1; bidx = idx1; }
    int stopi = stop0 | stop1;

    // Reduce across the 8 slots of this ego (consecutive lanes).
    #pragma unroll
    for (int m = 1; m <= 4; m <<= 1) {
        float ob = __shfl_xor_sync(0xFFFFFFFFu, best, m);
        int   oi = __shfl_xor_sync(0xFFFFFFFFu, bidx, m);
        int   os = __shfl_xor_sync(0xFFFFFFFFu, stopi, m);
        if (ob < best || (ob == best && oi < bidx)) { best = ob; bidx = oi; }
        stopi |= os;
    }

    if (slot == 0) {
        const float V0 = v0p[0], S0 = s0p[0], DTH = dthp[0];
        const float AMAX = amaxp[0], BB = bp[0];

        float4 ld = cand[bidx];
        float  vl = cv[bidx];
        float dvx = vl * ld.z - vj * cj;
        float dvy = vl * ld.w - vj * sj;
        float ndv = fmaf(dvx, cj, dvy * sj);   // dv * cos(vdelpsi), exact incl. dv=0

        float sal   = best - lengths[jl];
        float sstar = S0 + vj * DTH + (vj * ndv) / (2.0f * sqrtf(AMAX * BB));
        float q  = vj / V0;
        float q2 = q * q;
        float afree = AMAX * (1.0f - q2 * q2);

        float action;
        if (stopi) {
            action = afree - AMAX;                     // ratio = 1
        } else if (isinf(sal) || isnan(sal)) {
            action = afree;
        } else {
            float r = sstar / sal;
            action = afree - AMAX * r * r;
        }
        out[bat * NV + jl] = action;
    }
}

extern "C" void kernel_launch(void* const* d_in, const int* in_sizes, int n_in,
                              void* d_out, int out_size)
{
    const float* state   = (const float*)d_in[0];
    const float* lengths = (const float*)d_in[1];
    const float* v0      = (const float*)d_in[2];
    const float* s0      = (const float*)d_in[3];
    const float* dth     = (const float*)d_in[4];
    const float* amax    = (const float*)d_in[5];
    const float* b       = (const float*)d_in[6];
    float* out = (float*)d_out;

    prep_kernel<<<(NB * NV + 255) / 256, 256>>>(state);
    dim3 grid(NV / EGOS_PER_BLOCK, NB);
    rulepolicy_kernel<<<grid, THREADS>>>(lengths, v0, s0, dth, amax, b, out);
}

// round 5
// speedup vs baseline: 1.0938x; 1.0938x over previous
#include <cuda_runtime.h>
#include <math.h>

#define NV 1024
#define NB 16
#define GRID_DIM 16                 // 16x16 cells of 25m over [0,400)
#define NCELL (GRID_DIM * GRID_DIM)
#define EPB 32                      // egos per block
#define SLOTS 8
#define MTHREADS (EPB * SLOTS)      // 256

// Original-order data
__device__ float2 g_pos[NB * NV];         // {x, y}
__device__ float4 g_att[NB * NV];         // {cos, sin, v, 0}
// Cell-sorted per-batch data (for the stop neighborhood check)
__device__ float2 g_spos[NB * NV];
__device__ float4 g_satt[NB * NV];
__device__ int    g_cstart[NB * (NCELL + 1)];

// One block per batch: sincos + counting-sort into the 16x16 grid.
__global__ __launch_bounds__(512) void prep_kernel(const float* __restrict__ state)
{
    __shared__ int counts[NCELL];
    __shared__ int scan[NCELL];
    __shared__ int offs[NCELL];

    const int bat = blockIdx.x;
    const int t = threadIdx.x;
    const float* st = state + (size_t)bat * NV * 5;

    if (t < NCELL) counts[t] = 0;
    __syncthreads();

    float x[2], y[2], v[2], c[2], s[2];
    int cl[2];
    #pragma unroll
    for (int q = 0; q < 2; q++) {
        int i = t + q * 512;
        const float* p = st + i * 5;
        x[q] = p[0]; y[q] = p[1]; v[q] = p[2];
        float psi = p[3];
        sincosf(psi, &s[q], &c[q]);
        int cx = max(0, min(GRID_DIM - 1, (int)(x[q] * 0.04f)));
        int cy = max(0, min(GRID_DIM - 1, (int)(y[q] * 0.04f)));
        cl[q] = cy * GRID_DIM + cx;
        atomicAdd(&counts[cl[q]], 1);
        g_pos[bat * NV + i] = make_float2(x[q], y[q]);
        g_att[bat * NV + i] = make_float4(c[q], s[q], v[q], 0.0f);
    }
    __syncthreads();

    if (t < NCELL) scan[t] = counts[t];
    __syncthreads();
    for (int d = 1; d < NCELL; d <<= 1) {
        int val = 0;
        if (t < NCELL && t >= d) val = scan[t - d];
        __syncthreads();
        if (t < NCELL) scan[t] += val;
        __syncthreads();
    }
    if (t < NCELL) {
        int e = scan[t] - counts[t];           // exclusive
        offs[t] = e;
        g_cstart[bat * (NCELL + 1) + t] = e;
    }
    if (t == 0) g_cstart[bat * (NCELL + 1) + NCELL] = NV;
    __syncthreads();

    #pragma unroll
    for (int q = 0; q < 2; q++) {
        int pos = atomicAdd(&offs[cl[q]], 1);
        g_spos[bat * NV + pos] = make_float2(x[q], y[q]);
        g_satt[bat * NV + pos] = make_float4(c[q], s[q], v[q], 0.0f);
    }
}

__global__ __launch_bounds__(MTHREADS)
void rulepolicy_kernel(const float* __restrict__ lengths,
                       const float* __restrict__ v0p,
                       const float* __restrict__ s0p,
                       const float* __restrict__ dthp,
                       const float* __restrict__ amaxp,
                       const float* __restrict__ bp,
                       float* __restrict__ out)
{
    __shared__ float4 poso[NV / 2];        // original order, 2 vehicles per float4 (8 KB)
    __shared__ float2 spos[NV];            // sorted positions (8 KB)
    __shared__ float4 satt[NV];            // sorted attrs (16 KB)
    __shared__ int    cstart[NCELL + 1];

    const int bat = blockIdx.y;
    const int t = threadIdx.x;
    const int base = bat * NV;

    for (int i = t; i < NV / 2; i += MTHREADS) {
        poso[i] = ((const float4*)g_pos)[base / 2 + i];
        ((float4*)spos)[i] = ((const float4*)g_spos)[base / 2 + i];
    }
    for (int i = t; i < NV; i += MTHREADS) satt[i] = g_satt[base + i];
    if (t < NCELL + 1) cstart[t] = g_cstart[bat * (NCELL + 1) + t];
    __syncthreads();

    const int slot = t & (SLOTS - 1);
    const int jl   = blockIdx.x * EPB + (t >> 3);

    const float4 att = g_att[base + jl];
    const float cj = att.x, sj = att.y, vj = att.z;
    const float2 ep = g_pos[base + jl];
    const float xj = ep.x, yj = ep.y;

    const float C20SQ = 0.8830222215594891f;   // cos^2(20deg)
    const float C45   = 0.7071067811865476f;   // cos(45deg)
    const float INF   = __int_as_float(0x7f800000);

    // ── Leader scan over all 1024 in ORIGINAL order (exact R3 numerics) ──
    float best0 = INF, best1 = INF;
    int   idx0 = 0, idx1 = 0;

    #pragma unroll 8
    for (int k = slot; k < NV / 2; k += SLOTS) {
        float4 p = poso[k];

        float dx0 = p.x - xj, dy0 = p.y - yj;
        float r20 = fmaf(dx0, dx0, dy0 * dy0);
        float nd0 = fmaf(dx0, cj, dy0 * sj);      // dr * cos(delpsi)
        float m0  = fminf(nd0, fmaf(-C20SQ, r20, nd0 * nd0));
        float e0  = (m0 > 0.0f) ? nd0 : INF;
        if (e0 < best0) { best0 = e0; idx0 = 2 * k; }

        float dx1 = p.z - xj, dy1 = p.w - yj;
        float r21 = fmaf(dx1, dx1, dy1 * dy1);
        float nd1 = fmaf(dx1, cj, dy1 * sj);
        float m1  = fminf(nd1, fmaf(-C20SQ, r21, nd1 * nd1));
        float e1  = (m1 > 0.0f) ? nd1 : INF;
        if (e1 < best1) { best1 = e1; idx1 = 2 * k + 1; }
    }
    // Merge dual accumulators (tie -> smaller original index; idx0 < idx1 per iter).
    float best = best0; int bidx = idx0;
    if (best1 < best || (best1 == best && idx1 < bidx)) { best = best1; bidx = idx1; }

    // ── Stop check: 3x3 cell neighborhood only (~36 candidates) ──
    int stopi = 0;
    {
        int cx = max(0, min(GRID_DIM - 1, (int)(xj * 0.04f)));
        int cy = max(0, min(GRID_DIM - 1, (int)(yj * 0.04f)));
        int x0 = max(cx - 1, 0), x1 = min(cx + 1, GRID_DIM - 1);
        int y0 = max(cy - 1, 0), y1 = min(cy + 1, GRID_DIM - 1);
        for (int ry = y0; ry <= y1; ry++) {
            int beg = cstart[ry * GRID_DIM + x0];
            int end = cstart[ry * GRID_DIM + x1 + 1];
            for (int i = beg + slot; i < end; i += SLOTS) {
                float2 p = spos[i];
                float4 a = satt[i];
                float dx = p.x - xj, dy = p.y - yj;
                float r2 = fmaf(dx, dx, dy * dy);
                float nd = fmaf(dx, cj, dy * sj);
                float cpd = fmaf(a.x, cj, a.y * sj);  // cos(psi_i - psi_j)
                // dr<20 & |delpsi|<60 (nd>0 & nd^2>r2/4) & |dpsi|>45 & v_i>v_j
                stopi |= (int)((r2 < 400.0f) & (nd > 0.0f)
                               & (nd * nd > 0.25f * r2)
                               & (cpd < C45) & (a.z > vj));
            }
        }
    }

    // ── Reduce across the 8 slots of this ego (consecutive lanes) ──
    #pragma unroll
    for (int m = 1; m <= 4; m <<= 1) {
        float ob = __shfl_xor_sync(0xFFFFFFFFu, best, m);
        int   oi = __shfl_xor_sync(0xFFFFFFFFu, bidx, m);
        int   os = __shfl_xor_sync(0xFFFFFFFFu, stopi, m);
        if (ob < best || (ob == best && oi < bidx)) { best = ob; bidx = oi; }
        stopi |= os;
    }

    if (slot == 0) {
        const float V0 = v0p[0], S0 = s0p[0], DTH = dthp[0];
        const float AMAX = amaxp[0], BB = bp[0];

        float4 ld = g_att[base + bidx];         // {cos, sin, v} of leader (orig index)
        float dvx = ld.z * ld.x - vj * cj;
        float dvy = ld.z * ld.y - vj * sj;
        float ndv = fmaf(dvx, cj, dvy * sj);    // dv*cos(vdelpsi), exact incl. dv=0

        float sal   = best - lengths[jl];
        float sstar = S0 + vj * DTH + (vj * ndv) / (2.0f * sqrtf(AMAX * BB));
        float q  = vj / V0;
        float q2 = q * q;
        float afree = AMAX * (1.0f - q2 * q2);

        float action;
        if (stopi) {
            action = afree - AMAX;              // ratio = 1
        } else if (isinf(sal) || isnan(sal)) {
            action = afree;
        } else {
            float r = sstar / sal;
            action = afree - AMAX * r * r;
        }
        out[bat * NV + jl] = action;
    }
}

extern "C" void kernel_launch(void* const* d_in, const int* in_sizes, int n_in,
                              void* d_out, int out_size)
{
    const float* state   = (const float*)d_in[0];
    const float* lengths = (const float*)d_in[1];
    const float* v0      = (const float*)d_in[2];
    const float* s0      = (const float*)d_in[3];
    const float* dth     = (const float*)d_in[4];
    const float* amax    = (const float*)d_in[5];
    const float* b       = (const float*)d_in[6];
    float* out = (float*)d_out;

    prep_kernel<<<NB, 512>>>(state);
    dim3 grid(NV / EPB, NB);
    rulepolicy_kernel<<<grid, MTHREADS>>>(lengths, v0, s0, dth, amax, b, out);
}